// round 8
// baseline (speedup 1.0000x reference)
#include <cuda_runtime.h>
#include <cstdint>

#define MAX_SPIKE_TIME 100000.0f

// Problem constants (from reference setup_inputs)
static constexpr int B_SIZE   = 64;
static constexpr int IN_SIZE  = 1024;
static constexpr int NP1      = IN_SIZE + 1;   // 1025 (with appended 1.0)
static constexpr int OUT_SIZE = 512;
static constexpr int NSORT    = 1024;          // sort only the 1024 real inputs
static constexpr int THREADS  = 256;
static constexpr int J_PER_BLOCK = 256;        // outputs per block (2 blocks per batch)
static constexpr int PF       = 8;             // prefetch depth (reg ring buffer)
static constexpr int XI_SIZE  = NP1 + PF + 1;  // sorted array + sentinel/pad for prefetch

__global__ __launch_bounds__(THREADS, 2)
void snn_layer_kernel(const float* __restrict__ layer_in,
                      const float* __restrict__ weight,
                      const float* __restrict__ delay,
                      float* __restrict__ out)
{
    __shared__ unsigned long long sbuf[NSORT];  // 8 KB sort buffer
    __shared__ __align__(16) float2 xi[XI_SIZE]; // (sorted value, byte-offset bits) + pad
    __shared__ int s_pos;                       // insertion position of appended 1.0

    const int tid = threadIdx.x;
    const int b   = blockIdx.x >> 1;
    const int j   = ((blockIdx.x & 1) * J_PER_BLOCK) + tid;

    if (tid == 0) s_pos = 0;
    __syncthreads();

    // ---- Phase 1: build keys  key = (float_bits(x) << 32) | (index << 11) ----
    // x >= 0 so float-bit order == value order; (index<<11) is monotonic in
    // index, so low bits reproduce jnp.argsort's stable tie-break AND directly
    // encode the weight-row byte offset (row * 512 cols * 4 B = row << 11).
    // Count elements <= 1.0 to find the stable insertion position of the
    // appended (1.0, idx=1024): its index exceeds all others, so it lands
    // after every x <= 1.0.
    const float* lin = layer_in + (size_t)b * IN_SIZE;
    int cnt = 0;
    for (int i = tid; i < NSORT; i += THREADS) {
        float d  = delay[i];
        float xv = lin[i] * expf(fmaxf(d, 0.0f));   // accurate exp, matches jnp
        cnt += (xv <= 1.0f);
        sbuf[i] = ((unsigned long long)__float_as_uint(xv) << 32)
                | (unsigned)(i << 11);
    }
    if (cnt) atomicAdd(&s_pos, cnt);
    __syncthreads();

    // ---- Phase 2: bitonic sort (ascending) on 1024 uint64 keys ----
    for (int k = 2; k <= NSORT; k <<= 1) {
        for (int jj = k >> 1; jj > 0; jj >>= 1) {
            for (int i = tid; i < NSORT; i += THREADS) {
                int ixj = i ^ jj;
                if (ixj > i) {
                    unsigned long long a = sbuf[i];
                    unsigned long long c = sbuf[ixj];
                    bool up = ((i & k) == 0);
                    if ((a > c) == up) { sbuf[i] = c; sbuf[ixj] = a; }
                }
            }
            __syncthreads();
        }
    }

    // ---- Phase 3: unpack with insertion of (1.0, idx=1024) + pad ----
    const int pos = s_pos;
    for (int p = tid; p < NSORT; p += THREADS) {
        unsigned long long key = sbuf[p];
        int dest = p + (p >= pos);
        xi[dest] = make_float2(__uint_as_float((unsigned)(key >> 32)),
                               __uint_as_float((unsigned)(key & 0xffffffffu)));
    }
    if (tid == 0) xi[pos] = make_float2(1.0f, __uint_as_float(1024u << 11));
    // pad [NP1 .. XI_SIZE): sentinel + prefetch overrun (offset 0 = row 0, safe)
    if (NP1 + tid < XI_SIZE) xi[NP1 + tid] = make_float2(MAX_SPIKE_TIME, 0.0f);
    __syncthreads();

    // ---- Phase 4: division-free scan, PF-deep prefetch, slot-private bests ----
    // Quotient comparisons by cross-multiplication (denom > 0 always); the
    // running min is kept per unroll slot so its dependent chain has distance
    // PF iterations (fully hidden); one exact IEEE division at the end.
    float w_cum  = 0.0f;
    float wi_cum = 0.0f;
    float bnum[PF], bden[PF];
    #pragma unroll
    for (int u = 0; u < PF; ++u) { bnum[u] = MAX_SPIKE_TIME; bden[u] = 1.0f; }
    const char* Wj = (const char*)(weight + j);

    // preload PF weights (independent LDGs, all in flight together)
    float wbuf[PF];
    #pragma unroll
    for (int p = 0; p < PF; ++p) {
        unsigned off = __float_as_uint(xi[p].y);
        wbuf[p] = __ldg((const float*)(Wj + off));
    }

    float2 cur = xi[0];

    #pragma unroll 1
    for (int kb = 0; kb < IN_SIZE; kb += PF) {    // 1024 = 128 groups of 8
        #pragma unroll
        for (int u = 0; u < PF; ++u) {
            const int k = kb + u;
            float2 nxt = xi[k + 1];               // broadcast LDS.64
            float  w   = wbuf[u];
            // refill slot: issue LDG for iteration k+PF (consumed ~8 iters later)
            unsigned poff = __float_as_uint(xi[k + PF].y);
            wbuf[u] = __ldg((const float*)(Wj + poff));

            // mirror reference: ws*xs (unfused) then cumsum
            wi_cum = __fadd_rn(wi_cum, __fmul_rn(w, cur.x));
            w_cum  = __fadd_rn(w_cum, w);

            float denom = fmaxf(w_cum - 1.0f, 1e-10f);   // > 0 always

            // gates (cross-multiplied):
            //   cand >= xs[k]   <=> wi_cum >= xs[k]*denom
            //   cand <= xs[k+1] <=> wi_cum <= xs[k+1]*denom
            bool valid = (w_cum >= 1.0f)
                       & (wi_cum >= __fmul_rn(cur.x, denom))
                       & (wi_cum <= __fmul_rn(nxt.x, denom));
            // slot-private fraction min: wi_cum/denom < bnum[u]/bden[u]
            bool better = valid
                        & (__fmul_rn(wi_cum, bden[u]) < __fmul_rn(bnum[u], denom));
            if (better) { bnum[u] = wi_cum; bden[u] = denom; }

            cur = nxt;
        }
    }

    // epilogue: k = 1024 (wbuf[0] was refilled with row(xi[1024]) at kb=1016)
    {
        float2 nxt = xi[NP1];                     // MAX sentinel
        float  w   = wbuf[0];
        wi_cum = __fadd_rn(wi_cum, __fmul_rn(w, cur.x));
        w_cum  = __fadd_rn(w_cum, w);
        float denom = fmaxf(w_cum - 1.0f, 1e-10f);
        bool valid = (w_cum >= 1.0f)
                   & (wi_cum >= __fmul_rn(cur.x, denom))
                   & (wi_cum <= __fmul_rn(nxt.x, denom));
        bool better = valid
                    & (__fmul_rn(wi_cum, bden[0]) < __fmul_rn(bnum[0], denom));
        if (better) { bnum[0] = wi_cum; bden[0] = denom; }
    }

    // merge slot-private bests (7 cross-multiplied compares)
    float best_num = bnum[0], best_den = bden[0];
    #pragma unroll
    for (int u = 1; u < PF; ++u) {
        if (__fmul_rn(bnum[u], best_den) < __fmul_rn(best_num, bden[u])) {
            best_num = bnum[u]; best_den = bden[u];
        }
    }

    out[(size_t)b * OUT_SIZE + j] = best_num / best_den;   // one exact division
}

extern "C" void kernel_launch(void* const* d_in, const int* in_sizes, int n_in,
                              void* d_out, int out_size)
{
    const float* layer_in = (const float*)d_in[0];  // (64, 1024)
    const float* weight   = (const float*)d_in[1];  // (1025, 512)
    const float* delay    = (const float*)d_in[2];  // (1024,)
    float* out = (float*)d_out;                     // (64, 512)

    dim3 grid(B_SIZE * (OUT_SIZE / J_PER_BLOCK));   // 128 blocks
    dim3 block(THREADS);                            // 256 threads
    snn_layer_kernel<<<grid, block>>>(layer_in, weight, delay, out);
}

// round 9
// speedup vs baseline: 1.1286x; 1.1286x over previous
#include <cuda_runtime.h>
#include <cstdint>

#define MAX_SPIKE_TIME 100000.0f

// Problem constants (from reference setup_inputs)
static constexpr int B_SIZE   = 64;
static constexpr int IN_SIZE  = 1024;
static constexpr int NP1      = IN_SIZE + 1;   // 1025 (with appended 1.0)
static constexpr int OUT_SIZE = 512;
static constexpr int NSORT    = 1024;          // sort only the 1024 real inputs
static constexpr int THREADS  = 256;
static constexpr int J_PER_BLOCK = 256;        // outputs per block (2 blocks per batch)
static constexpr int PF       = 8;             // LDG prefetch distance (weight ring)
static constexpr int XR       = 16;            // xi LDS prefetch distance (register ring)
static constexpr int XI_SIZE  = NP1 + XR + 4;  // 1045: sorted array + sentinel/overrun pad

__global__ __launch_bounds__(THREADS, 2)
void snn_layer_kernel(const float* __restrict__ layer_in,
                      const float* __restrict__ weight,
                      const float* __restrict__ delay,
                      float* __restrict__ out)
{
    __shared__ unsigned long long sbuf[NSORT];   // 8 KB sort buffer
    __shared__ __align__(16) float2 xi[XI_SIZE]; // (sorted value, byte-offset bits) + pad
    __shared__ int s_pos;                        // insertion position of appended 1.0

    const int tid = threadIdx.x;
    const int b   = blockIdx.x >> 1;
    const int j   = ((blockIdx.x & 1) * J_PER_BLOCK) + tid;

    if (tid == 0) s_pos = 0;
    __syncthreads();

    // ---- Phase 1: build keys  key = (float_bits(x) << 32) | (index << 11) ----
    // x >= 0 so float-bit order == value order; (index<<11) is monotonic in
    // index, so low bits reproduce jnp.argsort's stable tie-break AND directly
    // encode the weight-row byte offset (row * 512 cols * 4 B = row << 11).
    // Count elements <= 1.0: stable insertion position of appended (1.0, 1024).
    const float* lin = layer_in + (size_t)b * IN_SIZE;
    int cnt = 0;
    for (int i = tid; i < NSORT; i += THREADS) {
        float d  = delay[i];
        float xv = lin[i] * expf(fmaxf(d, 0.0f));   // accurate exp, matches jnp
        cnt += (xv <= 1.0f);
        sbuf[i] = ((unsigned long long)__float_as_uint(xv) << 32)
                | (unsigned)(i << 11);
    }
    if (cnt) atomicAdd(&s_pos, cnt);
    __syncthreads();

    // ---- Phase 2: bitonic sort (ascending) on 1024 uint64 keys ----
    for (int k = 2; k <= NSORT; k <<= 1) {
        for (int jj = k >> 1; jj > 0; jj >>= 1) {
            for (int i = tid; i < NSORT; i += THREADS) {
                int ixj = i ^ jj;
                if (ixj > i) {
                    unsigned long long a = sbuf[i];
                    unsigned long long c = sbuf[ixj];
                    bool up = ((i & k) == 0);
                    if ((a > c) == up) { sbuf[i] = c; sbuf[ixj] = a; }
                }
            }
            __syncthreads();
        }
    }

    // ---- Phase 3: unpack with insertion of (1.0, idx=1024) + pad ----
    const int pos = s_pos;
    for (int p = tid; p < NSORT; p += THREADS) {
        unsigned long long key = sbuf[p];
        int dest = p + (p >= pos);
        xi[dest] = make_float2(__uint_as_float((unsigned)(key >> 32)),
                               __uint_as_float((unsigned)(key & 0xffffffffu)));
    }
    if (tid == 0) xi[pos] = make_float2(1.0f, __uint_as_float(1024u << 11));
    // pad [NP1 .. XI_SIZE): sentinel + ring overrun (offset 0 = row 0, safe)
    if (NP1 + tid < XI_SIZE) xi[NP1 + tid] = make_float2(MAX_SPIKE_TIME, 0.0f);
    __syncthreads();

    // ---- Phase 4: division-free scan, dual-distance register-ring prefetch ----
    // xr[] holds xi[k .. k+XR-1] in registers (LDS refill at distance XR=16,
    // 29-cyc shared latency fully hidden). The LDG address for weight k+PF is
    // taken from a ring entry loaded PF iterations earlier, so no LDS->LDG
    // dependence exists inside an iteration. Quotient comparisons by
    // cross-multiplication (denom > 0 always); one exact division at the end.
    float w_cum  = 0.0f;
    float wi_cum = 0.0f;
    float bnum[PF], bden[PF];
    #pragma unroll
    for (int u = 0; u < PF; ++u) { bnum[u] = MAX_SPIKE_TIME; bden[u] = 1.0f; }
    const char* Wj = (const char*)(weight + j);

    // warm-up: xi ring [0..15], weight ring [0..7]
    float2 xr[XR];
    #pragma unroll
    for (int p = 0; p < XR; ++p) xr[p] = xi[p];
    float wbuf[PF];
    #pragma unroll
    for (int p = 0; p < PF; ++p) {
        unsigned off = __float_as_uint(xr[p].y);
        wbuf[p] = __ldg((const float*)(Wj + off));
    }

    float2 cur = xr[0];

    #pragma unroll 1
    for (int kb = 0; kb < IN_SIZE; kb += XR) {    // 1024 = 64 groups of 16
        #pragma unroll
        for (int v = 0; v < XR; ++v) {
            const int k = kb + v;
            const int u = v & (PF - 1);
            float2 nxt = xr[(v + 1) & (XR - 1)];      // xi[k+1], in registers
            float  w   = wbuf[u];                      // W[row(xi[k])]

            // prefetch: LDG for iter k+PF, address from ring (LDS'd PF iters ago)
            unsigned poff = __float_as_uint(xr[(v + PF) & (XR - 1)].y);
            // refill ring slot v with xi[k+XR] (consumed XR iters from now)
            xr[v] = xi[k + XR];
            wbuf[u] = __ldg((const float*)(Wj + poff));

            // mirror reference: ws*xs (unfused) then cumsum
            wi_cum = __fadd_rn(wi_cum, __fmul_rn(w, cur.x));
            w_cum  = __fadd_rn(w_cum, w);

            float denom = fmaxf(w_cum - 1.0f, 1e-10f);   // > 0 always

            // gates (cross-multiplied):
            //   cand >= xs[k]   <=> wi_cum >= xs[k]*denom
            //   cand <= xs[k+1] <=> wi_cum <= xs[k+1]*denom
            bool valid = (w_cum >= 1.0f)
                       & (wi_cum >= __fmul_rn(cur.x, denom))
                       & (wi_cum <= __fmul_rn(nxt.x, denom));
            // slot-private fraction min: wi_cum/denom < bnum[u]/bden[u]
            bool better = valid
                        & (__fmul_rn(wi_cum, bden[u]) < __fmul_rn(bnum[u], denom));
            if (better) { bnum[u] = wi_cum; bden[u] = denom; }

            cur = nxt;
        }
    }

    // epilogue: k = 1024. cur = xi[1024] (carried); wbuf[0] was refilled at
    // k=1016 with W[row(xi[1024])]; nxt = MAX sentinel.
    {
        float2 nxt = xi[NP1];
        float  w   = wbuf[0];
        wi_cum = __fadd_rn(wi_cum, __fmul_rn(w, cur.x));
        w_cum  = __fadd_rn(w_cum, w);
        float denom = fmaxf(w_cum - 1.0f, 1e-10f);
        bool valid = (w_cum >= 1.0f)
                   & (wi_cum >= __fmul_rn(cur.x, denom))
                   & (wi_cum <= __fmul_rn(nxt.x, denom));
        bool better = valid
                    & (__fmul_rn(wi_cum, bden[0]) < __fmul_rn(bnum[0], denom));
        if (better) { bnum[0] = wi_cum; bden[0] = denom; }
    }

    // merge slot-private bests (7 cross-multiplied compares)
    float best_num = bnum[0], best_den = bden[0];
    #pragma unroll
    for (int u = 1; u < PF; ++u) {
        if (__fmul_rn(bnum[u], best_den) < __fmul_rn(best_num, bden[u])) {
            best_num = bnum[u]; best_den = bden[u];
        }
    }

    out[(size_t)b * OUT_SIZE + j] = best_num / best_den;   // one exact division
}

extern "C" void kernel_launch(void* const* d_in, const int* in_sizes, int n_in,
                              void* d_out, int out_size)
{
    const float* layer_in = (const float*)d_in[0];  // (64, 1024)
    const float* weight   = (const float*)d_in[1];  // (1025, 512)
    const float* delay    = (const float*)d_in[2];  // (1024,)
    float* out = (float*)d_out;                     // (64, 512)

    dim3 grid(B_SIZE * (OUT_SIZE / J_PER_BLOCK));   // 128 blocks
    dim3 block(THREADS);                            // 256 threads
    snn_layer_kernel<<<grid, block>>>(layer_in, weight, delay, out);
}